// round 3
// baseline (speedup 1.0000x reference)
#include <cuda_runtime.h>
#include <math.h>

#define N_MAX 100000
#define E_MAX 1600000

// ---------------- device scratch (static, no allocations) ----------------
__device__ __align__(256) float g_xw1[N_MAX * 64];   // x @ W1
__device__ __align__(256) float g_h1 [N_MAX * 64];   // relu(agg(xw1)+b1)
__device__ __align__(256) float g_agg[N_MAX * 64];   // agg(h1)
__device__ __align__(256) float g_h2 [N_MAX * 256];  // relu(agg@W2+b2)
__device__ __align__(256) float g_zw [N_MAX];        // h2 @ W3
__device__ __align__(256) float g_deg[N_MAX];        // dinv = rsqrt(deg)
__device__ int   g_cnt [N_MAX];
__device__ int   g_offs[N_MAX + 1];
__device__ int   g_pos [N_MAX];
__device__ int   g_esrc[E_MAX];
__device__ int   g_partial[1024];
__device__ float g_loss;

// ---------------- init ----------------
__global__ void init_k(int n) {
    int i = blockIdx.x * blockDim.x + threadIdx.x;
    if (i < n) g_cnt[i] = 0;
    if (i == 0) g_loss = 0.f;
}

// ---------------- degree histogram over dst ----------------
__global__ void count_k(const int* __restrict__ dst, int e) {
    int i = blockIdx.x * blockDim.x + threadIdx.x;
    if (i < e) atomicAdd(&g_cnt[dst[i]], 1);
}

// ---------------- 3-kernel exclusive scan of g_cnt -> g_offs ----------------
__global__ void scanA_k(int n) {
    __shared__ int sh[512];
    int i = blockIdx.x * 512 + threadIdx.x;
    sh[threadIdx.x] = (i < n) ? g_cnt[i] : 0;
    __syncthreads();
    for (int s = 256; s; s >>= 1) {
        if (threadIdx.x < s) sh[threadIdx.x] += sh[threadIdx.x + s];
        __syncthreads();
    }
    if (threadIdx.x == 0) g_partial[blockIdx.x] = sh[0];
}

__global__ void scanB_k(int nb) {   // single block of 1024 threads, nb <= 1024
    __shared__ int sh[1024];
    int t = threadIdx.x;
    int orig = (t < nb) ? g_partial[t] : 0;
    sh[t] = orig;
    __syncthreads();
    for (int off = 1; off < 1024; off <<= 1) {
        int v = (t >= off) ? sh[t - off] : 0;
        __syncthreads();
        sh[t] += v;
        __syncthreads();
    }
    if (t < nb) g_partial[t] = sh[t] - orig;   // exclusive
}

__global__ void scanC_k(int n, int e) {
    __shared__ int sh[512];
    int t = threadIdx.x;
    int i = blockIdx.x * 512 + t;
    int orig = (i < n) ? g_cnt[i] : 0;
    sh[t] = orig;
    __syncthreads();
    for (int off = 1; off < 512; off <<= 1) {
        int v = (t >= off) ? sh[t - off] : 0;
        __syncthreads();
        sh[t] += v;
        __syncthreads();
    }
    if (i < n) {
        int excl = sh[t] - orig + g_partial[blockIdx.x];
        g_offs[i] = excl;
        g_pos[i]  = excl;
        g_deg[i]  = rsqrtf((float)orig + 1.0f);   // dinv with self loop
    }
    if (i == 0) g_offs[n] = e;
}

// ---------------- CSR fill ----------------
__global__ void fill_k(const int* __restrict__ src, const int* __restrict__ dst, int e) {
    int i = blockIdx.x * blockDim.x + threadIdx.x;
    if (i < e) {
        int d = dst[i];
        int idx = atomicAdd(&g_pos[d], 1);
        g_esrc[idx] = src[i];
    }
}

// ---------------- GEMM1: C[n,64] = X[n,512] @ W[512,64] ----------------
__global__ void gemm1_k(const float* __restrict__ X, const float* __restrict__ W, int n) {
    __shared__ __align__(16) float Xs[32][68];   // [k][row], padded
    __shared__ __align__(16) float Ws[32][64];   // [k][col]
    int tid = threadIdx.x;
    int row0 = blockIdx.x * 64;
    int tx = tid & 15, ty = tid >> 4;
    float acc[4][4] = {};
    for (int k0 = 0; k0 < 512; k0 += 32) {
#pragma unroll
        for (int t = 0; t < 2; t++) {
            int f = tid + t * 256;            // 512 float4 total
            int r = f >> 3, kq = f & 7;
            int gr = row0 + r; if (gr >= n) gr = n - 1;
            float4 v = *(const float4*)(X + (size_t)gr * 512 + k0 + kq * 4);
            Xs[kq * 4 + 0][r] = v.x; Xs[kq * 4 + 1][r] = v.y;
            Xs[kq * 4 + 2][r] = v.z; Xs[kq * 4 + 3][r] = v.w;
        }
#pragma unroll
        for (int t = 0; t < 2; t++) {
            int f = tid + t * 256;            // 512 float4 total
            int kr = f >> 4, c4 = f & 15;
            *(float4*)&Ws[kr][c4 * 4] = *(const float4*)(W + (size_t)(k0 + kr) * 64 + c4 * 4);
        }
        __syncthreads();
#pragma unroll
        for (int kk = 0; kk < 32; kk++) {
            float4 a = *(const float4*)&Xs[kk][ty * 4];
            float4 b = *(const float4*)&Ws[kk][tx * 4];
            float ar[4] = {a.x, a.y, a.z, a.w};
            float br[4] = {b.x, b.y, b.z, b.w};
#pragma unroll
            for (int i = 0; i < 4; i++)
#pragma unroll
                for (int j = 0; j < 4; j++) acc[i][j] += ar[i] * br[j];
        }
        __syncthreads();
    }
#pragma unroll
    for (int i = 0; i < 4; i++) {
        int gr = row0 + ty * 4 + i;
        if (gr < n) {
#pragma unroll
            for (int j = 0; j < 4; j++) g_xw1[(size_t)gr * 64 + tx * 4 + j] = acc[i][j];
        }
    }
}

// ---------------- gather (64 features), warp per node ----------------
// which==0: in=g_xw1, out=g_h1, epilogue relu(+b1)
// which==1: in=g_h1,  out=g_agg, no epilogue
__global__ void gather64_k(int which, const float* __restrict__ bias, int n) {
    int w   = (blockIdx.x * blockDim.x + threadIdx.x) >> 5;
    int lid = threadIdx.x & 31;
    if (w >= n) return;
    const float* in = which ? g_h1 : g_xw1;
    float*       out = which ? g_agg : g_h1;
    float di = g_deg[w];
    float2 acc = ((const float2*)(in + (size_t)w * 64))[lid];
    acc.x *= di * di; acc.y *= di * di;           // self loop
    int p1 = g_offs[w + 1];
    for (int p = g_offs[w]; p < p1; p++) {
        int s = g_esrc[p];
        float wgt = g_deg[s] * di;
        float2 v = ((const float2*)(in + (size_t)s * 64))[lid];
        acc.x += v.x * wgt; acc.y += v.y * wgt;
    }
    if (which == 0) {
        acc.x = fmaxf(acc.x + bias[lid * 2],     0.f);
        acc.y = fmaxf(acc.y + bias[lid * 2 + 1], 0.f);
    }
    ((float2*)(out + (size_t)w * 64))[lid] = acc;
}

// ---------------- GEMM2: h2[n,256] = relu(agg[n,64] @ W2[64,256] + b2) ----------------
__global__ void gemm2_k(const float* __restrict__ W2, const float* __restrict__ b2, int n) {
    __shared__ __align__(16) float As[64][68];   // [k][row]
    __shared__ __align__(16) float Bs[64][64];   // [k][col]
    int tid = threadIdx.x;
    int row0 = blockIdx.x * 64;
    int col0 = blockIdx.y * 64;
    int tx = tid & 15, ty = tid >> 4;
#pragma unroll
    for (int t = 0; t < 4; t++) {                // A: 64x64 = 1024 float4
        int f = tid + t * 256;
        int r = f >> 4, k4 = f & 15;
        int gr = row0 + r; if (gr >= n) gr = n - 1;
        float4 v = *(const float4*)(g_agg + (size_t)gr * 64 + k4 * 4);
        As[k4 * 4 + 0][r] = v.x; As[k4 * 4 + 1][r] = v.y;
        As[k4 * 4 + 2][r] = v.z; As[k4 * 4 + 3][r] = v.w;
    }
#pragma unroll
    for (int t = 0; t < 4; t++) {                // B: 64x64 = 1024 float4
        int f = tid + t * 256;
        int kr = f >> 4, c4 = f & 15;
        *(float4*)&Bs[kr][c4 * 4] = *(const float4*)(W2 + (size_t)kr * 256 + col0 + c4 * 4);
    }
    __syncthreads();
    float acc[4][4] = {};
#pragma unroll
    for (int kk = 0; kk < 64; kk++) {
        float4 a = *(const float4*)&As[kk][ty * 4];
        float4 b = *(const float4*)&Bs[kk][tx * 4];
        float ar[4] = {a.x, a.y, a.z, a.w};
        float br[4] = {b.x, b.y, b.z, b.w};
#pragma unroll
        for (int i = 0; i < 4; i++)
#pragma unroll
            for (int j = 0; j < 4; j++) acc[i][j] += ar[i] * br[j];
    }
#pragma unroll
    for (int i = 0; i < 4; i++) {
        int gr = row0 + ty * 4 + i;
        if (gr < n) {
#pragma unroll
            for (int j = 0; j < 4; j++) {
                int c = col0 + tx * 4 + j;
                g_h2[(size_t)gr * 256 + c] = fmaxf(acc[i][j] + b2[c], 0.f);
            }
        }
    }
}

// ---------------- zw[n] = h2[n,256] @ W3[256] ----------------
__global__ void zw_k(const float* __restrict__ W3, int n) {
    __shared__ float w[256];
    w[threadIdx.x] = W3[threadIdx.x];
    __syncthreads();
    int i   = blockIdx.x * 8 + (threadIdx.x >> 5);
    int lid = threadIdx.x & 31;
    if (i >= n) return;
    const float4* h = (const float4*)(g_h2 + (size_t)i * 256);
    float4 a = h[lid], b = h[lid + 32];
    const float4* wv = (const float4*)w;
    float4 wa = wv[lid], wb = wv[lid + 32];
    float s = a.x * wa.x + a.y * wa.y + a.z * wa.z + a.w * wa.w
            + b.x * wb.x + b.y * wb.y + b.z * wb.z + b.w * wb.w;
#pragma unroll
    for (int off = 16; off; off >>= 1) s += __shfl_xor_sync(0xffffffffu, s, off);
    if (lid == 0) g_zw[i] = s;
}

// ---------------- layer-3 gather + BCE + reduce ----------------
__global__ void loss_k(const float* __restrict__ y, const float* __restrict__ b3, int n) {
    int i = blockIdx.x * 256 + threadIdx.x;
    float l = 0.f;
    if (i < n) {
        float di = g_deg[i];
        float acc = g_zw[i] * di * di;
        int p1 = g_offs[i + 1];
        for (int p = g_offs[i]; p < p1; p++) {
            int s = g_esrc[p];
            acc += g_zw[s] * g_deg[s] * di;
        }
        float zi = acc + b3[0];
        float yi = y[i];
        float l1p = log1pf(expf(-fabsf(zi)));
        float sp_pos = fmaxf(zi,  0.f) + l1p;    // softplus(z)
        float sp_neg = fmaxf(-zi, 0.f) + l1p;    // softplus(-z)
        l = yi * sp_neg + (1.f - yi) * sp_pos;
    }
    __shared__ float sh[256];
    sh[threadIdx.x] = l;
    __syncthreads();
    for (int s = 128; s; s >>= 1) {
        if (threadIdx.x < s) sh[threadIdx.x] += sh[threadIdx.x + s];
        __syncthreads();
    }
    if (threadIdx.x == 0) atomicAdd(&g_loss, sh[0]);
}

__global__ void finalize_k(float* out, int n) {
    out[0] = g_loss * (1.0f / (float)n);
}

// ---------------- launch ----------------
extern "C" void kernel_launch(void* const* d_in, const int* in_sizes, int n_in,
                              void* d_out, int out_size) {
    const float* x  = (const float*)d_in[0];
    const int*   ei = (const int*)  d_in[1];
    const float* y  = (const float*)d_in[2];
    const float* W1 = (const float*)d_in[3];
    const float* b1 = (const float*)d_in[4];
    const float* W2 = (const float*)d_in[5];
    const float* b2 = (const float*)d_in[6];
    const float* W3 = (const float*)d_in[7];
    const float* b3 = (const float*)d_in[8];
    float* out = (float*)d_out;

    int n = in_sizes[0] / 512;
    int e = in_sizes[1] / 2;
    const int* src = ei;
    const int* dst = ei + e;

    int nb = (n + 511) / 512;   // scan blocks (196 for n=100000, <= 1024)

    init_k <<<(n + 255) / 256, 256>>>(n);
    count_k<<<(e + 255) / 256, 256>>>(dst, e);
    scanA_k<<<nb, 512>>>(n);
    scanB_k<<<1, 1024>>>(nb);
    scanC_k<<<nb, 512>>>(n, e);
    fill_k <<<(e + 255) / 256, 256>>>(src, dst, e);

    gemm1_k<<<(n + 63) / 64, 256>>>(x, W1, n);
    gather64_k<<<(n + 7) / 8, 256>>>(0, b1, n);           // h1 = relu(A xw1 + b1)
    gather64_k<<<(n + 7) / 8, 256>>>(1, b1, n);           // agg = A h1
    {
        dim3 grid((n + 63) / 64, 4);
        gemm2_k<<<grid, 256>>>(W2, b2, n);                // h2 = relu(agg @ W2 + b2)
    }
    zw_k  <<<(n + 7) / 8, 256>>>(W3, n);                  // zw = h2 @ W3
    loss_k<<<(n + 255) / 256, 256>>>(y, b3, n);           // z = A zw + b3 ; BCE ; sum
    finalize_k<<<1, 1>>>(out, n);
}

// round 5
// speedup vs baseline: 2.0178x; 2.0178x over previous
#include <cuda_runtime.h>
#include <cuda_bf16.h>
#include <cstdint>
#include <math.h>

#define N_MAX 100000
#define E_MAX 1600000

// ---------------- device scratch (static, no allocations) ----------------
__device__ __align__(256) float g_xw1[N_MAX * 64];          // x @ W1  (f32)
__device__ __align__(256) float g_h1 [N_MAX * 64];          // relu(agg(xw1)+b1)
__device__ __align__(256) __nv_bfloat16 g_aggb[N_MAX * 64]; // agg(h1) in bf16
__device__ __align__(256) float g_zw [N_MAX];               // fused gemm2+W3 output
__device__ __align__(256) float g_deg[N_MAX];               // dinv = rsqrt(deg)
__device__ int   g_cnt [N_MAX];
__device__ int   g_offs[N_MAX + 1];
__device__ int   g_pos [N_MAX];
__device__ int   g_esrc[E_MAX];
__device__ int   g_partial[1024];
__device__ float g_loss;

// ---------------- helpers ----------------
__device__ __forceinline__ uint32_t smem_u32(const void* p) {
    uint32_t a;
    asm("{ .reg .u64 t; cvta.to.shared.u64 t, %1; cvt.u32.u64 %0, t; }" : "=r"(a) : "l"(p));
    return a;
}

#define LDSM_X4(R0,R1,R2,R3,ADDR) \
    asm volatile("ldmatrix.sync.aligned.m8n8.x4.shared.b16 {%0,%1,%2,%3}, [%4];" \
        : "=r"(R0),"=r"(R1),"=r"(R2),"=r"(R3) : "r"(ADDR))

#define LDSM_X4T(R0,R1,R2,R3,ADDR) \
    asm volatile("ldmatrix.sync.aligned.m8n8.x4.trans.shared.b16 {%0,%1,%2,%3}, [%4];" \
        : "=r"(R0),"=r"(R1),"=r"(R2),"=r"(R3) : "r"(ADDR))

#define MMA_BF16(D,A0,A1,A2,A3,B0,B1) \
    asm volatile("mma.sync.aligned.m16n8k16.row.col.f32.bf16.bf16.f32 " \
        "{%0,%1,%2,%3}, {%4,%5,%6,%7}, {%8,%9}, {%0,%1,%2,%3};" \
        : "+f"((D)[0]),"+f"((D)[1]),"+f"((D)[2]),"+f"((D)[3]) \
        : "r"(A0),"r"(A1),"r"(A2),"r"(A3),"r"(B0),"r"(B1))

// ---------------- init ----------------
__global__ void init_k(int n) {
    int i = blockIdx.x * blockDim.x + threadIdx.x;
    if (i < n) g_cnt[i] = 0;
    if (i == 0) g_loss = 0.f;
}

__global__ void count_k(const int* __restrict__ dst, int e) {
    int i = blockIdx.x * blockDim.x + threadIdx.x;
    if (i < e) atomicAdd(&g_cnt[dst[i]], 1);
}

// ---------------- 3-kernel exclusive scan ----------------
__global__ void scanA_k(int n) {
    __shared__ int sh[512];
    int i = blockIdx.x * 512 + threadIdx.x;
    sh[threadIdx.x] = (i < n) ? g_cnt[i] : 0;
    __syncthreads();
    for (int s = 256; s; s >>= 1) {
        if (threadIdx.x < s) sh[threadIdx.x] += sh[threadIdx.x + s];
        __syncthreads();
    }
    if (threadIdx.x == 0) g_partial[blockIdx.x] = sh[0];
}

__global__ void scanB_k(int nb) {
    __shared__ int sh[1024];
    int t = threadIdx.x;
    int orig = (t < nb) ? g_partial[t] : 0;
    sh[t] = orig;
    __syncthreads();
    for (int off = 1; off < 1024; off <<= 1) {
        int v = (t >= off) ? sh[t - off] : 0;
        __syncthreads();
        sh[t] += v;
        __syncthreads();
    }
    if (t < nb) g_partial[t] = sh[t] - orig;
}

__global__ void scanC_k(int n, int e) {
    __shared__ int sh[512];
    int t = threadIdx.x;
    int i = blockIdx.x * 512 + t;
    int orig = (i < n) ? g_cnt[i] : 0;
    sh[t] = orig;
    __syncthreads();
    for (int off = 1; off < 512; off <<= 1) {
        int v = (t >= off) ? sh[t - off] : 0;
        __syncthreads();
        sh[t] += v;
        __syncthreads();
    }
    if (i < n) {
        int excl = sh[t] - orig + g_partial[blockIdx.x];
        g_offs[i] = excl;
        g_pos[i]  = excl;
        g_deg[i]  = rsqrtf((float)orig + 1.0f);
    }
    if (i == 0) g_offs[n] = e;
}

__global__ void fill_k(const int* __restrict__ src, const int* __restrict__ dst, int e) {
    int i = blockIdx.x * blockDim.x + threadIdx.x;
    if (i < e) {
        int d = dst[i];
        int idx = atomicAdd(&g_pos[d], 1);
        g_esrc[idx] = src[i];
    }
}

// ---------------- GEMM1 (HMMA): xw1[128-tile,64] = X[.,512] @ W1[512,64] ----------------
// SMEM: A [128][72] bf16, B [64][72] bf16 (stride 72 halves = 144B, ldmatrix conflict-free)
__global__ void __launch_bounds__(256) gemm1_mma(const float* __restrict__ X,
                                                 const float* __restrict__ W1, int n) {
    __shared__ __align__(16) __nv_bfloat16 As[128 * 72];
    __shared__ __align__(16) __nv_bfloat16 Bs[64 * 72];
    int tid  = threadIdx.x;
    int wid  = tid >> 5, lane = tid & 31;
    int row0 = blockIdx.x * 128;
    int wrow = wid * 16;

    uint32_t abase = smem_u32(As);
    uint32_t bbase = smem_u32(Bs);
    // per-thread ldmatrix address bases
    uint32_t a_addr0 = abase + (uint32_t)(wrow + (lane & 15)) * 144u + (uint32_t)(lane >> 4) * 16u;
    uint32_t b_addr0 = bbase + (uint32_t)((lane & 7) + ((lane >> 3) & 1) * 8) * 144u
                             + (uint32_t)(lane >> 4) * 16u;

    float acc[8][4] = {};

    for (int c = 0; c < 8; c++) {
        int k0 = c * 64;
        // stage A: 128 rows x 64 f32 -> bf16  (2048 float4 loads)
#pragma unroll
        for (int it = 0; it < 8; it++) {
            int f = tid + it * 256;
            int r = f >> 4, q = f & 15;
            int gr = row0 + r; if (gr >= n) gr = n - 1;
            float4 v = *(const float4*)(X + (size_t)gr * 512 + k0 + q * 4);
            __nv_bfloat162 lo = __float22bfloat162_rn(make_float2(v.x, v.y));
            __nv_bfloat162 hi = __float22bfloat162_rn(make_float2(v.z, v.w));
            uint2 u; u.x = *(uint32_t*)&lo; u.y = *(uint32_t*)&hi;
            *(uint2*)(As + r * 72 + q * 4) = u;
        }
        // stage B: W1 chunk [64][64] f32 -> bf16 (1024 float4)
#pragma unroll
        for (int it = 0; it < 4; it++) {
            int f = tid + it * 256;
            int kr = f >> 4, q = f & 15;
            float4 v = *(const float4*)(W1 + (size_t)(k0 + kr) * 64 + q * 4);
            __nv_bfloat162 lo = __float22bfloat162_rn(make_float2(v.x, v.y));
            __nv_bfloat162 hi = __float22bfloat162_rn(make_float2(v.z, v.w));
            uint2 u; u.x = *(uint32_t*)&lo; u.y = *(uint32_t*)&hi;
            *(uint2*)(Bs + kr * 72 + q * 4) = u;
        }
        __syncthreads();
#pragma unroll
        for (int ks = 0; ks < 4; ks++) {
            uint32_t a0, a1, a2, a3;
            LDSM_X4(a0, a1, a2, a3, a_addr0 + (uint32_t)ks * 32u);
            uint32_t b[8][2];
#pragma unroll
            for (int g = 0; g < 4; g++) {
                LDSM_X4T(b[2 * g][0], b[2 * g][1], b[2 * g + 1][0], b[2 * g + 1][1],
                         b_addr0 + (uint32_t)ks * 16u * 144u + (uint32_t)g * 32u);
            }
#pragma unroll
            for (int j = 0; j < 8; j++) MMA_BF16(acc[j], a0, a1, a2, a3, b[j][0], b[j][1]);
        }
        __syncthreads();
    }
    // epilogue: write f32
    int rbase = row0 + wrow + (lane >> 2);
    int cbase = (lane & 3) * 2;
#pragma unroll
    for (int j = 0; j < 8; j++) {
        int col = j * 8 + cbase;
        if (rbase < n) {
            g_xw1[(size_t)rbase * 64 + col]     = acc[j][0];
            g_xw1[(size_t)rbase * 64 + col + 1] = acc[j][1];
        }
        if (rbase + 8 < n) {
            g_xw1[(size_t)(rbase + 8) * 64 + col]     = acc[j][2];
            g_xw1[(size_t)(rbase + 8) * 64 + col + 1] = acc[j][3];
        }
    }
}

// ---------------- gathers (64 feats), warp per node ----------------
__global__ void gather_h1(const float* __restrict__ bias, int n) {
    int w   = (blockIdx.x * blockDim.x + threadIdx.x) >> 5;
    int lid = threadIdx.x & 31;
    if (w >= n) return;
    float di = g_deg[w];
    float2 acc = ((const float2*)(g_xw1 + (size_t)w * 64))[lid];
    acc.x *= di * di; acc.y *= di * di;
    int p1 = g_offs[w + 1];
    for (int p = g_offs[w]; p < p1; p++) {
        int s = g_esrc[p];
        float wgt = g_deg[s] * di;
        float2 v = ((const float2*)(g_xw1 + (size_t)s * 64))[lid];
        acc.x += v.x * wgt; acc.y += v.y * wgt;
    }
    acc.x = fmaxf(acc.x + bias[lid * 2],     0.f);
    acc.y = fmaxf(acc.y + bias[lid * 2 + 1], 0.f);
    ((float2*)(g_h1 + (size_t)w * 64))[lid] = acc;
}

__global__ void gather_agg(int n) {
    int w   = (blockIdx.x * blockDim.x + threadIdx.x) >> 5;
    int lid = threadIdx.x & 31;
    if (w >= n) return;
    float di = g_deg[w];
    float2 acc = ((const float2*)(g_h1 + (size_t)w * 64))[lid];
    acc.x *= di * di; acc.y *= di * di;
    int p1 = g_offs[w + 1];
    for (int p = g_offs[w]; p < p1; p++) {
        int s = g_esrc[p];
        float wgt = g_deg[s] * di;
        float2 v = ((const float2*)(g_h1 + (size_t)s * 64))[lid];
        acc.x += v.x * wgt; acc.y += v.y * wgt;
    }
    ((__nv_bfloat162*)(g_aggb + (size_t)w * 64))[lid] = __float22bfloat162_rn(acc);
}

// ---------------- GEMM2 (HMMA) fused: zw[row] = relu(aggb@W2 + b2) . W3 ----------------
// dyn SMEM: A [128][72] bf16 @0 (18432 B), B [64][264] bf16 @18432 (33792 B),
//           b2 f32[256] @52224, w3 f32[256] @53248; total 54272 B
#define G2_SMEM 54272

__global__ void __launch_bounds__(256) gemm2_mma(const float* __restrict__ W2,
                                                 const float* __restrict__ b2,
                                                 const float* __restrict__ W3, int n) {
    extern __shared__ char smem[];
    __nv_bfloat16* As  = (__nv_bfloat16*)(smem);
    __nv_bfloat16* Bs  = (__nv_bfloat16*)(smem + 18432);
    float*         b2s = (float*)(smem + 52224);
    float*         w3s = (float*)(smem + 53248);

    int tid  = threadIdx.x;
    int wid  = tid >> 5, lane = tid & 31;
    int row0 = blockIdx.x * 128;
    int wrow = wid * 16;

    // stage A: 128 rows x 64 bf16 (already bf16)
#pragma unroll
    for (int it = 0; it < 8; it++) {
        int f = tid + it * 256;
        int r = f >> 4, q = f & 15;
        int gr = row0 + r; if (gr >= n) gr = n - 1;
        uint2 u = ((const uint2*)(g_aggb + (size_t)gr * 64))[q];
        *(uint2*)(As + r * 72 + q * 4) = u;
    }
    // stage B: W2 [64][256] f32 -> bf16 (4096 float4)
#pragma unroll
    for (int it = 0; it < 16; it++) {
        int f = tid + it * 256;
        int kr = f >> 6, q = f & 63;
        float4 v = *(const float4*)(W2 + (size_t)kr * 256 + q * 4);
        __nv_bfloat162 lo = __float22bfloat162_rn(make_float2(v.x, v.y));
        __nv_bfloat162 hi = __float22bfloat162_rn(make_float2(v.z, v.w));
        uint2 u; u.x = *(uint32_t*)&lo; u.y = *(uint32_t*)&hi;
        *(uint2*)(Bs + kr * 264 + q * 4) = u;
    }
    b2s[tid] = b2[tid];
    w3s[tid] = W3[tid];
    __syncthreads();

    uint32_t abase = smem_u32(As);
    uint32_t bbase = smem_u32(Bs);
    uint32_t a_addr0 = abase + (uint32_t)(wrow + (lane & 15)) * 144u + (uint32_t)(lane >> 4) * 16u;
    uint32_t b_addr0 = bbase + (uint32_t)((lane & 7) + ((lane >> 3) & 1) * 8) * 528u
                             + (uint32_t)(lane >> 4) * 16u;

    float rs0 = 0.f, rs1 = 0.f;   // row dot-sums for rows (wrow+lane/4) and +8

#pragma unroll
    for (int cg = 0; cg < 4; cg++) {
        float acc[8][4] = {};
#pragma unroll
        for (int ks = 0; ks < 4; ks++) {
            uint32_t a0, a1, a2, a3;
            LDSM_X4(a0, a1, a2, a3, a_addr0 + (uint32_t)ks * 32u);
            uint32_t b[8][2];
#pragma unroll
            for (int g = 0; g < 4; g++) {
                LDSM_X4T(b[2 * g][0], b[2 * g][1], b[2 * g + 1][0], b[2 * g + 1][1],
                         b_addr0 + (uint32_t)ks * 16u * 528u + (uint32_t)cg * 128u + (uint32_t)g * 32u);
            }
#pragma unroll
            for (int j = 0; j < 8; j++) MMA_BF16(acc[j], a0, a1, a2, a3, b[j][0], b[j][1]);
        }
        // epilogue: relu(+b2) . w3, accumulate
#pragma unroll
        for (int j = 0; j < 8; j++) {
            int col = cg * 64 + j * 8 + (lane & 3) * 2;
            float v;
            v = fmaxf(acc[j][0] + b2s[col],     0.f); rs0 += v * w3s[col];
            v = fmaxf(acc[j][1] + b2s[col + 1], 0.f); rs0 += v * w3s[col + 1];
            v = fmaxf(acc[j][2] + b2s[col],     0.f); rs1 += v * w3s[col];
            v = fmaxf(acc[j][3] + b2s[col + 1], 0.f); rs1 += v * w3s[col + 1];
        }
    }
    // quad reduce (lanes 4k..4k+3 share a row)
    rs0 += __shfl_xor_sync(0xffffffffu, rs0, 1);
    rs0 += __shfl_xor_sync(0xffffffffu, rs0, 2);
    rs1 += __shfl_xor_sync(0xffffffffu, rs1, 1);
    rs1 += __shfl_xor_sync(0xffffffffu, rs1, 2);
    if ((lane & 3) == 0) {
        int r = row0 + wrow + (lane >> 2);
        if (r < n)     g_zw[r]     = rs0;
        if (r + 8 < n) g_zw[r + 8] = rs1;
    }
}

// ---------------- layer-3 gather + BCE + reduce ----------------
__global__ void loss_k(const float* __restrict__ y, const float* __restrict__ b3, int n) {
    int i = blockIdx.x * 256 + threadIdx.x;
    float l = 0.f;
    if (i < n) {
        float di = g_deg[i];
        float acc = g_zw[i] * di * di;
        int p1 = g_offs[i + 1];
        for (int p = g_offs[i]; p < p1; p++) {
            int s = g_esrc[p];
            acc += g_zw[s] * g_deg[s] * di;
        }
        float zi = acc + b3[0];
        float yi = y[i];
        float l1p = log1pf(expf(-fabsf(zi)));
        float sp_pos = fmaxf(zi,  0.f) + l1p;
        float sp_neg = fmaxf(-zi, 0.f) + l1p;
        l = yi * sp_neg + (1.f - yi) * sp_pos;
    }
    __shared__ float sh[256];
    sh[threadIdx.x] = l;
    __syncthreads();
    for (int s = 128; s; s >>= 1) {
        if (threadIdx.x < s) sh[threadIdx.x] += sh[threadIdx.x + s];
        __syncthreads();
    }
    if (threadIdx.x == 0) atomicAdd(&g_loss, sh[0]);
}

__global__ void finalize_k(float* out, int n) {
    out[0] = g_loss * (1.0f / (float)n);
}

// ---------------- launch ----------------
extern "C" void kernel_launch(void* const* d_in, const int* in_sizes, int n_in,
                              void* d_out, int out_size) {
    const float* x  = (const float*)d_in[0];
    const int*   ei = (const int*)  d_in[1];
    const float* y  = (const float*)d_in[2];
    const float* W1 = (const float*)d_in[3];
    const float* b1 = (const float*)d_in[4];
    const float* W2 = (const float*)d_in[5];
    const float* b2 = (const float*)d_in[6];
    const float* W3 = (const float*)d_in[7];
    const float* b3 = (const float*)d_in[8];
    float* out = (float*)d_out;

    int n = in_sizes[0] / 512;
    int e = in_sizes[1] / 2;
    const int* src = ei;
    const int* dst = ei + e;

    int nb = (n + 511) / 512;

    cudaFuncSetAttribute(gemm2_mma, cudaFuncAttributeMaxDynamicSharedMemorySize, G2_SMEM);

    init_k <<<(n + 255) / 256, 256>>>(n);
    count_k<<<(e + 255) / 256, 256>>>(dst, e);
    scanA_k<<<nb, 512>>>(n);
    scanB_k<<<1, 1024>>>(nb);
    scanC_k<<<nb, 512>>>(n, e);
    fill_k <<<(e + 255) / 256, 256>>>(src, dst, e);

    gemm1_mma<<<(n + 127) / 128, 256>>>(x, W1, n);
    gather_h1 <<<(n + 7) / 8, 256>>>(b1, n);    // h1 = relu(A xw1 + b1)
    gather_agg<<<(n + 7) / 8, 256>>>(n);        // aggb = bf16(A h1)
    gemm2_mma<<<(n + 127) / 128, 256, G2_SMEM>>>(W2, b2, W3, n);
    loss_k<<<(n + 255) / 256, 256>>>(y, b3, n);
    finalize_k<<<1, 1>>>(out, n);
}

// round 6
// speedup vs baseline: 2.0181x; 1.0001x over previous
#include <cuda_runtime.h>
#include <cuda_bf16.h>
#include <cstdint>
#include <math.h>

#define N_MAX 100000
#define E_MAX 1600000

// ---------------- device scratch (static, no allocations) ----------------
__device__ __align__(256) __nv_bfloat16 g_xw1b[N_MAX * 64]; // x @ W1 (bf16)
__device__ __align__(256) __nv_bfloat16 g_h1b [N_MAX * 64]; // relu(agg(xw1)+b1) (bf16)
__device__ __align__(256) __nv_bfloat16 g_aggb[N_MAX * 64]; // agg(h1) (bf16)
__device__ __align__(256) float g_zw [N_MAX];               // fused gemm2+W3 output
__device__ __align__(256) float g_deg[N_MAX];               // dinv = rsqrt(deg)
__device__ int   g_cnt [N_MAX];
__device__ int   g_offs[N_MAX + 1];
__device__ int   g_pos [N_MAX];
__device__ int   g_esrc[E_MAX];
__device__ int   g_partial[1024];
__device__ float g_loss;

// ---------------- helpers ----------------
__device__ __forceinline__ uint32_t smem_u32(const void* p) {
    uint32_t a;
    asm("{ .reg .u64 t; cvta.to.shared.u64 t, %1; cvt.u32.u64 %0, t; }" : "=r"(a) : "l"(p));
    return a;
}

#define LDSM_X4(R0,R1,R2,R3,ADDR) \
    asm volatile("ldmatrix.sync.aligned.m8n8.x4.shared.b16 {%0,%1,%2,%3}, [%4];" \
        : "=r"(R0),"=r"(R1),"=r"(R2),"=r"(R3) : "r"(ADDR))

#define LDSM_X4T(R0,R1,R2,R3,ADDR) \
    asm volatile("ldmatrix.sync.aligned.m8n8.x4.trans.shared.b16 {%0,%1,%2,%3}, [%4];" \
        : "=r"(R0),"=r"(R1),"=r"(R2),"=r"(R3) : "r"(ADDR))

#define MMA_BF16(D,A0,A1,A2,A3,B0,B1) \
    asm volatile("mma.sync.aligned.m16n8k16.row.col.f32.bf16.bf16.f32 " \
        "{%0,%1,%2,%3}, {%4,%5,%6,%7}, {%8,%9}, {%0,%1,%2,%3};" \
        : "+f"((D)[0]),"+f"((D)[1]),"+f"((D)[2]),"+f"((D)[3]) \
        : "r"(A0),"r"(A1),"r"(A2),"r"(A3),"r"(B0),"r"(B1))

// ---------------- init ----------------
__global__ void init_k(int n) {
    int i = blockIdx.x * blockDim.x + threadIdx.x;
    if (i < n) g_cnt[i] = 0;
    if (i == 0) g_loss = 0.f;
}

__global__ void count_k(const int* __restrict__ dst, int e) {
    int i = blockIdx.x * blockDim.x + threadIdx.x;
    if (i < e) atomicAdd(&g_cnt[dst[i]], 1);
}

// ---------------- 3-kernel exclusive scan ----------------
__global__ void scanA_k(int n) {
    __shared__ int sh[512];
    int i = blockIdx.x * 512 + threadIdx.x;
    sh[threadIdx.x] = (i < n) ? g_cnt[i] : 0;
    __syncthreads();
    for (int s = 256; s; s >>= 1) {
        if (threadIdx.x < s) sh[threadIdx.x] += sh[threadIdx.x + s];
        __syncthreads();
    }
    if (threadIdx.x == 0) g_partial[blockIdx.x] = sh[0];
}

__global__ void scanB_k(int nb) {
    __shared__ int sh[1024];
    int t = threadIdx.x;
    int orig = (t < nb) ? g_partial[t] : 0;
    sh[t] = orig;
    __syncthreads();
    for (int off = 1; off < 1024; off <<= 1) {
        int v = (t >= off) ? sh[t - off] : 0;
        __syncthreads();
        sh[t] += v;
        __syncthreads();
    }
    if (t < nb) g_partial[t] = sh[t] - orig;
}

__global__ void scanC_k(int n, int e) {
    __shared__ int sh[512];
    int t = threadIdx.x;
    int i = blockIdx.x * 512 + t;
    int orig = (i < n) ? g_cnt[i] : 0;
    sh[t] = orig;
    __syncthreads();
    for (int off = 1; off < 512; off <<= 1) {
        int v = (t >= off) ? sh[t - off] : 0;
        __syncthreads();
        sh[t] += v;
        __syncthreads();
    }
    if (i < n) {
        int excl = sh[t] - orig + g_partial[blockIdx.x];
        g_offs[i] = excl;
        g_pos[i]  = excl;
        g_deg[i]  = rsqrtf((float)orig + 1.0f);
    }
    if (i == 0) g_offs[n] = e;
}

__global__ void fill_k(const int* __restrict__ src, const int* __restrict__ dst, int e) {
    int i = blockIdx.x * blockDim.x + threadIdx.x;
    if (i < e) {
        int d = dst[i];
        int idx = atomicAdd(&g_pos[d], 1);
        g_esrc[idx] = src[i];
    }
}

// ---------------- GEMM1 (HMMA, double-buffered): xw1b = bf16(X @ W1) ----------------
// dyn SMEM: A0 @0 (18432), A1 @18432, B0 @36864 (9216), B1 @46080; total 55296
#define G1_SMEM 55296

__global__ void __launch_bounds__(256) gemm1_mma(const float* __restrict__ X,
                                                 const float* __restrict__ W1, int n) {
    extern __shared__ char smem[];
    __nv_bfloat16* Abuf[2] = {(__nv_bfloat16*)(smem),         (__nv_bfloat16*)(smem + 18432)};
    __nv_bfloat16* Bbuf[2] = {(__nv_bfloat16*)(smem + 36864), (__nv_bfloat16*)(smem + 46080)};

    int tid  = threadIdx.x;
    int wid  = tid >> 5, lane = tid & 31;
    int row0 = blockIdx.x * 128;
    int wrow = wid * 16;

    // per-thread ldmatrix bases for both buffers
    uint32_t a_base[2], b_base[2];
#pragma unroll
    for (int b = 0; b < 2; b++) {
        a_base[b] = smem_u32(Abuf[b]) + (uint32_t)(wrow + (lane & 15)) * 144u + (uint32_t)(lane >> 4) * 16u;
        b_base[b] = smem_u32(Bbuf[b]) + (uint32_t)((lane & 7) + ((lane >> 3) & 1) * 8) * 144u
                                      + (uint32_t)(lane >> 4) * 16u;
    }

    // staging coordinates
    int ar[8], aq[8];
    const float* aptr[8];
#pragma unroll
    for (int it = 0; it < 8; it++) {
        int f = tid + it * 256;
        ar[it] = f >> 4; aq[it] = f & 15;
        int gr = row0 + ar[it]; if (gr >= n) gr = n - 1;
        aptr[it] = X + (size_t)gr * 512 + aq[it] * 4;
    }
    int bkr[4], bq[4];
#pragma unroll
    for (int it = 0; it < 4; it++) {
        int f = tid + it * 256;
        bkr[it] = f >> 4; bq[it] = f & 15;
    }

    float4 pa[8], pb[4];
    // prefetch chunk 0
#pragma unroll
    for (int it = 0; it < 8; it++) pa[it] = *(const float4*)(aptr[it]);
#pragma unroll
    for (int it = 0; it < 4; it++) pb[it] = *(const float4*)(W1 + (size_t)bkr[it] * 64 + bq[it] * 4);

    float acc[8][4] = {};

    for (int c = 0; c < 8; c++) {
        int buf = c & 1;
        // store prefetched chunk
        __nv_bfloat16* As = Abuf[buf];
        __nv_bfloat16* Bs = Bbuf[buf];
#pragma unroll
        for (int it = 0; it < 8; it++) {
            __nv_bfloat162 lo = __float22bfloat162_rn(make_float2(pa[it].x, pa[it].y));
            __nv_bfloat162 hi = __float22bfloat162_rn(make_float2(pa[it].z, pa[it].w));
            uint2 u; u.x = *(uint32_t*)&lo; u.y = *(uint32_t*)&hi;
            *(uint2*)(As + ar[it] * 72 + aq[it] * 4) = u;
        }
#pragma unroll
        for (int it = 0; it < 4; it++) {
            __nv_bfloat162 lo = __float22bfloat162_rn(make_float2(pb[it].x, pb[it].y));
            __nv_bfloat162 hi = __float22bfloat162_rn(make_float2(pb[it].z, pb[it].w));
            uint2 u; u.x = *(uint32_t*)&lo; u.y = *(uint32_t*)&hi;
            *(uint2*)(Bs + bkr[it] * 72 + bq[it] * 4) = u;
        }
        __syncthreads();
        // prefetch next chunk (overlaps MMA below)
        if (c < 7) {
            int k0 = (c + 1) * 64;
#pragma unroll
            for (int it = 0; it < 8; it++) pa[it] = *(const float4*)(aptr[it] + k0);
#pragma unroll
            for (int it = 0; it < 4; it++)
                pb[it] = *(const float4*)(W1 + (size_t)(k0 + bkr[it]) * 64 + bq[it] * 4);
        }
        // MMA on current buffer
#pragma unroll
        for (int ks = 0; ks < 4; ks++) {
            uint32_t a0, a1, a2, a3;
            LDSM_X4(a0, a1, a2, a3, a_base[buf] + (uint32_t)ks * 32u);
            uint32_t b[8][2];
#pragma unroll
            for (int g = 0; g < 4; g++) {
                LDSM_X4T(b[2 * g][0], b[2 * g][1], b[2 * g + 1][0], b[2 * g + 1][1],
                         b_base[buf] + (uint32_t)ks * 16u * 144u + (uint32_t)g * 32u);
            }
#pragma unroll
            for (int j = 0; j < 8; j++) MMA_BF16(acc[j], a0, a1, a2, a3, b[j][0], b[j][1]);
        }
        __syncthreads();
    }
    // epilogue: write bf16
    int rbase = row0 + wrow + (lane >> 2);
    int cbase = (lane & 3) * 2;
#pragma unroll
    for (int j = 0; j < 8; j++) {
        int col = j * 8 + cbase;
        if (rbase < n) {
            __nv_bfloat162 v = __float22bfloat162_rn(make_float2(acc[j][0], acc[j][1]));
            *(uint32_t*)(g_xw1b + (size_t)rbase * 64 + col) = *(uint32_t*)&v;
        }
        if (rbase + 8 < n) {
            __nv_bfloat162 v = __float22bfloat162_rn(make_float2(acc[j][2], acc[j][3]));
            *(uint32_t*)(g_xw1b + (size_t)(rbase + 8) * 64 + col) = *(uint32_t*)&v;
        }
    }
}

// ---------------- gathers (64 bf16 feats = 128B rows), warp per node ----------------
__global__ void gather_h1(const float* __restrict__ bias, int n) {
    int w   = (blockIdx.x * blockDim.x + threadIdx.x) >> 5;
    int lid = threadIdx.x & 31;
    if (w >= n) return;
    float di = g_deg[w];
    uint32_t u = ((const uint32_t*)(g_xw1b + (size_t)w * 64))[lid];
    float2 self = __bfloat1622float2(*(__nv_bfloat162*)&u);
    float2 acc;
    acc.x = self.x * di * di; acc.y = self.y * di * di;
    int p  = g_offs[w];
    int p1 = g_offs[w + 1];
#pragma unroll 2
    for (; p < p1; p++) {
        int s = g_esrc[p];
        float wgt = g_deg[s] * di;
        uint32_t uv = ((const uint32_t*)(g_xw1b + (size_t)s * 64))[lid];
        float2 v = __bfloat1622float2(*(__nv_bfloat162*)&uv);
        acc.x += v.x * wgt; acc.y += v.y * wgt;
    }
    acc.x = fmaxf(acc.x + bias[lid * 2],     0.f);
    acc.y = fmaxf(acc.y + bias[lid * 2 + 1], 0.f);
    __nv_bfloat162 o = __float22bfloat162_rn(acc);
    ((uint32_t*)(g_h1b + (size_t)w * 64))[lid] = *(uint32_t*)&o;
}

__global__ void gather_agg(int n) {
    int w   = (blockIdx.x * blockDim.x + threadIdx.x) >> 5;
    int lid = threadIdx.x & 31;
    if (w >= n) return;
    float di = g_deg[w];
    uint32_t u = ((const uint32_t*)(g_h1b + (size_t)w * 64))[lid];
    float2 self = __bfloat1622float2(*(__nv_bfloat162*)&u);
    float2 acc;
    acc.x = self.x * di * di; acc.y = self.y * di * di;
    int p  = g_offs[w];
    int p1 = g_offs[w + 1];
#pragma unroll 2
    for (; p < p1; p++) {
        int s = g_esrc[p];
        float wgt = g_deg[s] * di;
        uint32_t uv = ((const uint32_t*)(g_h1b + (size_t)s * 64))[lid];
        float2 v = __bfloat1622float2(*(__nv_bfloat162*)&uv);
        acc.x += v.x * wgt; acc.y += v.y * wgt;
    }
    __nv_bfloat162 o = __float22bfloat162_rn(acc);
    ((uint32_t*)(g_aggb + (size_t)w * 64))[lid] = *(uint32_t*)&o;
}

// ---------------- GEMM2 (HMMA) fused: zw[row] = relu(aggb@W2 + b2) . W3 ----------------
// dyn SMEM: A [128][72] bf16 @0 (18432 B), B [64][264] bf16 @18432 (33792 B),
//           b2 f32[256] @52224, w3 f32[256] @53248; total 54272 B
#define G2_SMEM 54272

__global__ void __launch_bounds__(256) gemm2_mma(const float* __restrict__ W2,
                                                 const float* __restrict__ b2,
                                                 const float* __restrict__ W3, int n) {
    extern __shared__ char smem[];
    __nv_bfloat16* As  = (__nv_bfloat16*)(smem);
    __nv_bfloat16* Bs  = (__nv_bfloat16*)(smem + 18432);
    float*         b2s = (float*)(smem + 52224);
    float*         w3s = (float*)(smem + 53248);

    int tid  = threadIdx.x;
    int wid  = tid >> 5, lane = tid & 31;
    int row0 = blockIdx.x * 128;
    int wrow = wid * 16;

    // stage A: 128 rows x 64 bf16
#pragma unroll
    for (int it = 0; it < 8; it++) {
        int f = tid + it * 256;
        int r = f >> 4, q = f & 15;
        int gr = row0 + r; if (gr >= n) gr = n - 1;
        uint2 u = ((const uint2*)(g_aggb + (size_t)gr * 64))[q];
        *(uint2*)(As + r * 72 + q * 4) = u;
    }
    // stage B: W2 [64][256] f32 -> bf16 (4096 float4)
#pragma unroll
    for (int it = 0; it < 16; it++) {
        int f = tid + it * 256;
        int kr = f >> 6, q = f & 63;
        float4 v = *(const float4*)(W2 + (size_t)kr * 256 + q * 4);
        __nv_bfloat162 lo = __float22bfloat162_rn(make_float2(v.x, v.y));
        __nv_bfloat162 hi = __float22bfloat162_rn(make_float2(v.z, v.w));
        uint2 u; u.x = *(uint32_t*)&lo; u.y = *(uint32_t*)&hi;
        *(uint2*)(Bs + kr * 264 + q * 4) = u;
    }
    b2s[tid] = b2[tid];
    w3s[tid] = W3[tid];
    __syncthreads();

    uint32_t abase = smem_u32(As);
    uint32_t bbase = smem_u32(Bs);
    uint32_t a_addr0 = abase + (uint32_t)(wrow + (lane & 15)) * 144u + (uint32_t)(lane >> 4) * 16u;
    uint32_t b_addr0 = bbase + (uint32_t)((lane & 7) + ((lane >> 3) & 1) * 8) * 528u
                             + (uint32_t)(lane >> 4) * 16u;

    float rs0 = 0.f, rs1 = 0.f;

#pragma unroll
    for (int cg = 0; cg < 4; cg++) {
        float acc[8][4] = {};
#pragma unroll
        for (int ks = 0; ks < 4; ks++) {
            uint32_t a0, a1, a2, a3;
            LDSM_X4(a0, a1, a2, a3, a_addr0 + (uint32_t)ks * 32u);
            uint32_t b[8][2];
#pragma unroll
            for (int g = 0; g < 4; g++) {
                LDSM_X4T(b[2 * g][0], b[2 * g][1], b[2 * g + 1][0], b[2 * g + 1][1],
                         b_addr0 + (uint32_t)ks * 16u * 528u + (uint32_t)cg * 128u + (uint32_t)g * 32u);
            }
#pragma unroll
            for (int j = 0; j < 8; j++) MMA_BF16(acc[j], a0, a1, a2, a3, b[j][0], b[j][1]);
        }
#pragma unroll
        for (int j = 0; j < 8; j++) {
            int col = cg * 64 + j * 8 + (lane & 3) * 2;
            float v;
            v = fmaxf(acc[j][0] + b2s[col],     0.f); rs0 += v * w3s[col];
            v = fmaxf(acc[j][1] + b2s[col + 1], 0.f); rs0 += v * w3s[col + 1];
            v = fmaxf(acc[j][2] + b2s[col],     0.f); rs1 += v * w3s[col];
            v = fmaxf(acc[j][3] + b2s[col + 1], 0.f); rs1 += v * w3s[col + 1];
        }
    }
    rs0 += __shfl_xor_sync(0xffffffffu, rs0, 1);
    rs0 += __shfl_xor_sync(0xffffffffu, rs0, 2);
    rs1 += __shfl_xor_sync(0xffffffffu, rs1, 1);
    rs1 += __shfl_xor_sync(0xffffffffu, rs1, 2);
    if ((lane & 3) == 0) {
        int r = row0 + wrow + (lane >> 2);
        if (r < n)     g_zw[r]     = rs0;
        if (r + 8 < n) g_zw[r + 8] = rs1;
    }
}

// ---------------- layer-3 gather + BCE + reduce ----------------
__global__ void loss_k(const float* __restrict__ y, const float* __restrict__ b3, int n) {
    int i = blockIdx.x * 256 + threadIdx.x;
    float l = 0.f;
    if (i < n) {
        float di = g_deg[i];
        float acc = g_zw[i] * di * di;
        int p1 = g_offs[i + 1];
        for (int p = g_offs[i]; p < p1; p++) {
            int s = g_esrc[p];
            acc += g_zw[s] * g_deg[s] * di;
        }
        float zi = acc + b3[0];
        float yi = y[i];
        float l1p = log1pf(expf(-fabsf(zi)));
        float sp_pos = fmaxf(zi,  0.f) + l1p;
        float sp_neg = fmaxf(-zi, 0.f) + l1p;
        l = yi * sp_neg + (1.f - yi) * sp_pos;
    }
    __shared__ float sh[256];
    sh[threadIdx.x] = l;
    __syncthreads();
    for (int s = 128; s; s >>= 1) {
        if (threadIdx.x < s) sh[threadIdx.x] += sh[threadIdx.x + s];
        __syncthreads();
    }
    if (threadIdx.x == 0) atomicAdd(&g_loss, sh[0]);
}

__global__ void finalize_k(float* out, int n) {
    out[0] = g_loss * (1.0f / (float)n);
}

// ---------------- launch ----------------
extern "C" void kernel_launch(void* const* d_in, const int* in_sizes, int n_in,
                              void* d_out, int out_size) {
    const float* x  = (const float*)d_in[0];
    const int*   ei = (const int*)  d_in[1];
    const float* y  = (const float*)d_in[2];
    const float* W1 = (const float*)d_in[3];
    const float* b1 = (const float*)d_in[4];
    const float* W2 = (const float*)d_in[5];
    const float* b2 = (const float*)d_in[6];
    const float* W3 = (const float*)d_in[7];
    const float* b3 = (const float*)d_in[8];
    float* out = (float*)d_out;

    int n = in_sizes[0] / 512;
    int e = in_sizes[1] / 2;
    const int* src = ei;
    const int* dst = ei + e;

    int nb = (n + 511) / 512;

    cudaFuncSetAttribute(gemm1_mma, cudaFuncAttributeMaxDynamicSharedMemorySize, G1_SMEM);
    cudaFuncSetAttribute(gemm2_mma, cudaFuncAttributeMaxDynamicSharedMemorySize, G2_SMEM);

    init_k <<<(n + 255) / 256, 256>>>(n);
    count_k<<<(e + 255) / 256, 256>>>(dst, e);
    scanA_k<<<nb, 512>>>(n);
    scanB_k<<<1, 1024>>>(nb);
    scanC_k<<<nb, 512>>>(n, e);
    fill_k <<<(e + 255) / 256, 256>>>(src, dst, e);

    gemm1_mma<<<(n + 127) / 128, 256, G1_SMEM>>>(x, W1, n);
    gather_h1 <<<(n + 7) / 8, 256>>>(b1, n);    // h1b = bf16(relu(A xw1 + b1))
    gather_agg<<<(n + 7) / 8, 256>>>(n);        // aggb = bf16(A h1)
    gemm2_mma<<<(n + 127) / 128, 256, G2_SMEM>>>(W2, b2, W3, n);
    loss_k<<<(n + 255) / 256, 256>>>(y, b3, n);
    finalize_k<<<1, 1>>>(out, n);
}

// round 7
// speedup vs baseline: 2.1641x; 1.0724x over previous
#include <cuda_runtime.h>
#include <cuda_bf16.h>
#include <cstdint>
#include <math.h>

#define N_MAX 100000
#define E_MAX 1600000

// ---------------- device scratch (static, no allocations) ----------------
__device__ __align__(256) __nv_bfloat16 g_xw1b[N_MAX * 64]; // x @ W1 (bf16)
__device__ __align__(256) __nv_bfloat16 g_h1b [N_MAX * 64]; // relu(agg(xw1)+b1) (bf16)
__device__ __align__(256) __nv_bfloat16 g_aggb[N_MAX * 64]; // agg(h1) (bf16)
__device__ __align__(256) float g_zw [N_MAX];               // fused gemm2+W3 output
__device__ __align__(256) float g_deg[N_MAX];               // dinv = rsqrt(deg)
__device__ int   g_cnt [N_MAX];
__device__ int   g_offs[N_MAX + 1];
__device__ int   g_pos [N_MAX];
__device__ int   g_esrc[E_MAX];
__device__ int   g_partial[1024];
__device__ float g_lpart[512];

// ---------------- static streams/events (created at load, before baseline) ----------------
struct SideStream {
    cudaStream_t s1;
    cudaEvent_t  e0, e1;
    SideStream() {
        cudaStreamCreateWithFlags(&s1, cudaStreamNonBlocking);
        cudaEventCreateWithFlags(&e0, cudaEventDisableTiming);
        cudaEventCreateWithFlags(&e1, cudaEventDisableTiming);
    }
};
static SideStream g_ss;

// ---------------- helpers ----------------
__device__ __forceinline__ uint32_t smem_u32(const void* p) {
    uint32_t a;
    asm("{ .reg .u64 t; cvta.to.shared.u64 t, %1; cvt.u32.u64 %0, t; }" : "=r"(a) : "l"(p));
    return a;
}

#define LDSM_X4(R0,R1,R2,R3,ADDR) \
    asm volatile("ldmatrix.sync.aligned.m8n8.x4.shared.b16 {%0,%1,%2,%3}, [%4];" \
        : "=r"(R0),"=r"(R1),"=r"(R2),"=r"(R3) : "r"(ADDR))

#define LDSM_X4T(R0,R1,R2,R3,ADDR) \
    asm volatile("ldmatrix.sync.aligned.m8n8.x4.trans.shared.b16 {%0,%1,%2,%3}, [%4];" \
        : "=r"(R0),"=r"(R1),"=r"(R2),"=r"(R3) : "r"(ADDR))

#define MMA_BF16(D,A0,A1,A2,A3,B0,B1) \
    asm volatile("mma.sync.aligned.m16n8k16.row.col.f32.bf16.bf16.f32 " \
        "{%0,%1,%2,%3}, {%4,%5,%6,%7}, {%8,%9}, {%0,%1,%2,%3};" \
        : "+f"((D)[0]),"+f"((D)[1]),"+f"((D)[2]),"+f"((D)[3]) \
        : "r"(A0),"r"(A1),"r"(A2),"r"(A3),"r"(B0),"r"(B1))

// ---------------- preprocessing ----------------
__global__ void init_k(int n) {
    int i = blockIdx.x * blockDim.x + threadIdx.x;
    if (i < n) g_cnt[i] = 0;
}

__global__ void count_k(const int* __restrict__ dst, int e) {
    int i = blockIdx.x * blockDim.x + threadIdx.x;
    if (i < e) atomicAdd(&g_cnt[dst[i]], 1);
}

__global__ void scanA_k(int n) {
    __shared__ int sh[512];
    int i = blockIdx.x * 512 + threadIdx.x;
    sh[threadIdx.x] = (i < n) ? g_cnt[i] : 0;
    __syncthreads();
    for (int s = 256; s; s >>= 1) {
        if (threadIdx.x < s) sh[threadIdx.x] += sh[threadIdx.x + s];
        __syncthreads();
    }
    if (threadIdx.x == 0) g_partial[blockIdx.x] = sh[0];
}

// scanC: per-block prefix over partials (nb <= 512) + intra-block scan; no scanB needed
__global__ void scanC_k(int n, int e) {
    __shared__ int pre[512];
    __shared__ int sh[512];
    int t = threadIdx.x;
    pre[t] = (t < (int)blockIdx.x) ? g_partial[t] : 0;
    __syncthreads();
    for (int s = 256; s; s >>= 1) {
        if (t < s) pre[t] += pre[t + s];
        __syncthreads();
    }
    int blockOff = pre[0];

    int i = blockIdx.x * 512 + t;
    int orig = (i < n) ? g_cnt[i] : 0;
    sh[t] = orig;
    __syncthreads();
    for (int off = 1; off < 512; off <<= 1) {
        int v = (t >= off) ? sh[t - off] : 0;
        __syncthreads();
        sh[t] += v;
        __syncthreads();
    }
    if (i < n) {
        int excl = sh[t] - orig + blockOff;
        g_offs[i] = excl;
        g_pos[i]  = excl;
        g_deg[i]  = rsqrtf((float)orig + 1.0f);
    }
    if (i == 0) g_offs[n] = e;
}

__global__ void fill_k(const int* __restrict__ src, const int* __restrict__ dst, int e) {
    int i = blockIdx.x * blockDim.x + threadIdx.x;
    if (i < e) {
        int d = dst[i];
        int idx = atomicAdd(&g_pos[d], 1);
        g_esrc[idx] = src[i];
    }
}

// ---------------- GEMM1 (HMMA, double-buffered): xw1b = bf16(X @ W1) ----------------
#define G1_SMEM 55296

__global__ void __launch_bounds__(256) gemm1_mma(const float* __restrict__ X,
                                                 const float* __restrict__ W1, int n) {
    extern __shared__ char smem[];
    __nv_bfloat16* Abuf[2] = {(__nv_bfloat16*)(smem),         (__nv_bfloat16*)(smem + 18432)};
    __nv_bfloat16* Bbuf[2] = {(__nv_bfloat16*)(smem + 36864), (__nv_bfloat16*)(smem + 46080)};

    int tid  = threadIdx.x;
    int wid  = tid >> 5, lane = tid & 31;
    int row0 = blockIdx.x * 128;
    int wrow = wid * 16;

    uint32_t a_base[2], b_base[2];
#pragma unroll
    for (int b = 0; b < 2; b++) {
        a_base[b] = smem_u32(Abuf[b]) + (uint32_t)(wrow + (lane & 15)) * 144u + (uint32_t)(lane >> 4) * 16u;
        b_base[b] = smem_u32(Bbuf[b]) + (uint32_t)((lane & 7) + ((lane >> 3) & 1) * 8) * 144u
                                      + (uint32_t)(lane >> 4) * 16u;
    }

    int ar[8], aq[8];
    const float* aptr[8];
#pragma unroll
    for (int it = 0; it < 8; it++) {
        int f = tid + it * 256;
        ar[it] = f >> 4; aq[it] = f & 15;
        int gr = row0 + ar[it]; if (gr >= n) gr = n - 1;
        aptr[it] = X + (size_t)gr * 512 + aq[it] * 4;
    }
    int bkr[4], bq[4];
#pragma unroll
    for (int it = 0; it < 4; it++) {
        int f = tid + it * 256;
        bkr[it] = f >> 4; bq[it] = f & 15;
    }

    float4 pa[8], pb[4];
#pragma unroll
    for (int it = 0; it < 8; it++) pa[it] = *(const float4*)(aptr[it]);
#pragma unroll
    for (int it = 0; it < 4; it++) pb[it] = *(const float4*)(W1 + (size_t)bkr[it] * 64 + bq[it] * 4);

    float acc[8][4] = {};

    for (int c = 0; c < 8; c++) {
        int buf = c & 1;
        __nv_bfloat16* As = Abuf[buf];
        __nv_bfloat16* Bs = Bbuf[buf];
#pragma unroll
        for (int it = 0; it < 8; it++) {
            __nv_bfloat162 lo = __float22bfloat162_rn(make_float2(pa[it].x, pa[it].y));
            __nv_bfloat162 hi = __float22bfloat162_rn(make_float2(pa[it].z, pa[it].w));
            uint2 u; u.x = *(uint32_t*)&lo; u.y = *(uint32_t*)&hi;
            *(uint2*)(As + ar[it] * 72 + aq[it] * 4) = u;
        }
#pragma unroll
        for (int it = 0; it < 4; it++) {
            __nv_bfloat162 lo = __float22bfloat162_rn(make_float2(pb[it].x, pb[it].y));
            __nv_bfloat162 hi = __float22bfloat162_rn(make_float2(pb[it].z, pb[it].w));
            uint2 u; u.x = *(uint32_t*)&lo; u.y = *(uint32_t*)&hi;
            *(uint2*)(Bs + bkr[it] * 72 + bq[it] * 4) = u;
        }
        __syncthreads();
        if (c < 7) {
            int k0 = (c + 1) * 64;
#pragma unroll
            for (int it = 0; it < 8; it++) pa[it] = *(const float4*)(aptr[it] + k0);
#pragma unroll
            for (int it = 0; it < 4; it++)
                pb[it] = *(const float4*)(W1 + (size_t)(k0 + bkr[it]) * 64 + bq[it] * 4);
        }
#pragma unroll
        for (int ks = 0; ks < 4; ks++) {
            uint32_t a0, a1, a2, a3;
            LDSM_X4(a0, a1, a2, a3, a_base[buf] + (uint32_t)ks * 32u);
            uint32_t b[8][2];
#pragma unroll
            for (int g = 0; g < 4; g++) {
                LDSM_X4T(b[2 * g][0], b[2 * g][1], b[2 * g + 1][0], b[2 * g + 1][1],
                         b_base[buf] + (uint32_t)ks * 16u * 144u + (uint32_t)g * 32u);
            }
#pragma unroll
            for (int j = 0; j < 8; j++) MMA_BF16(acc[j], a0, a1, a2, a3, b[j][0], b[j][1]);
        }
        __syncthreads();
    }
    int rbase = row0 + wrow + (lane >> 2);
    int cbase = (lane & 3) * 2;
#pragma unroll
    for (int j = 0; j < 8; j++) {
        int col = j * 8 + cbase;
        if (rbase < n) {
            __nv_bfloat162 v = __float22bfloat162_rn(make_float2(acc[j][0], acc[j][1]));
            *(uint32_t*)(g_xw1b + (size_t)rbase * 64 + col) = *(uint32_t*)&v;
        }
        if (rbase + 8 < n) {
            __nv_bfloat162 v = __float22bfloat162_rn(make_float2(acc[j][2], acc[j][3]));
            *(uint32_t*)(g_xw1b + (size_t)(rbase + 8) * 64 + col) = *(uint32_t*)&v;
        }
    }
}

// ---------------- gathers (64 bf16 feats = 128B rows), warp per node ----------------
__global__ void gather_h1(const float* __restrict__ bias, int n) {
    int w   = (blockIdx.x * blockDim.x + threadIdx.x) >> 5;
    int lid = threadIdx.x & 31;
    if (w >= n) return;
    float di = g_deg[w];
    uint32_t u = ((const uint32_t*)(g_xw1b + (size_t)w * 64))[lid];
    float2 self = __bfloat1622float2(*(__nv_bfloat162*)&u);
    float2 acc;
    acc.x = self.x * di * di; acc.y = self.y * di * di;
    int p  = g_offs[w];
    int p1 = g_offs[w + 1];
#pragma unroll 2
    for (; p < p1; p++) {
        int s = g_esrc[p];
        float wgt = g_deg[s] * di;
        uint32_t uv = ((const uint32_t*)(g_xw1b + (size_t)s * 64))[lid];
        float2 v = __bfloat1622float2(*(__nv_bfloat162*)&uv);
        acc.x += v.x * wgt; acc.y += v.y * wgt;
    }
    acc.x = fmaxf(acc.x + bias[lid * 2],     0.f);
    acc.y = fmaxf(acc.y + bias[lid * 2 + 1], 0.f);
    __nv_bfloat162 o = __float22bfloat162_rn(acc);
    ((uint32_t*)(g_h1b + (size_t)w * 64))[lid] = *(uint32_t*)&o;
}

__global__ void gather_agg(int n) {
    int w   = (blockIdx.x * blockDim.x + threadIdx.x) >> 5;
    int lid = threadIdx.x & 31;
    if (w >= n) return;
    float di = g_deg[w];
    uint32_t u = ((const uint32_t*)(g_h1b + (size_t)w * 64))[lid];
    float2 self = __bfloat1622float2(*(__nv_bfloat162*)&u);
    float2 acc;
    acc.x = self.x * di * di; acc.y = self.y * di * di;
    int p  = g_offs[w];
    int p1 = g_offs[w + 1];
#pragma unroll 2
    for (; p < p1; p++) {
        int s = g_esrc[p];
        float wgt = g_deg[s] * di;
        uint32_t uv = ((const uint32_t*)(g_h1b + (size_t)s * 64))[lid];
        float2 v = __bfloat1622float2(*(__nv_bfloat162*)&uv);
        acc.x += v.x * wgt; acc.y += v.y * wgt;
    }
    __nv_bfloat162 o = __float22bfloat162_rn(acc);
    ((uint32_t*)(g_aggb + (size_t)w * 64))[lid] = *(uint32_t*)&o;
}

// ---------------- GEMM2 (HMMA) fused: zw[row] = relu(aggb@W2 + b2) . W3 ----------------
#define G2_SMEM 54272

__global__ void __launch_bounds__(256) gemm2_mma(const float* __restrict__ W2,
                                                 const float* __restrict__ b2,
                                                 const float* __restrict__ W3, int n) {
    extern __shared__ char smem[];
    __nv_bfloat16* As  = (__nv_bfloat16*)(smem);
    __nv_bfloat16* Bs  = (__nv_bfloat16*)(smem + 18432);
    float*         b2s = (float*)(smem + 52224);
    float*         w3s = (float*)(smem + 53248);

    int tid  = threadIdx.x;
    int wid  = tid >> 5, lane = tid & 31;
    int row0 = blockIdx.x * 128;
    int wrow = wid * 16;

#pragma unroll
    for (int it = 0; it < 8; it++) {
        int f = tid + it * 256;
        int r = f >> 4, q = f & 15;
        int gr = row0 + r; if (gr >= n) gr = n - 1;
        uint2 u = ((const uint2*)(g_aggb + (size_t)gr * 64))[q];
        *(uint2*)(As + r * 72 + q * 4) = u;
    }
#pragma unroll
    for (int it = 0; it < 16; it++) {
        int f = tid + it * 256;
        int kr = f >> 6, q = f & 63;
        float4 v = *(const float4*)(W2 + (size_t)kr * 256 + q * 4);
        __nv_bfloat162 lo = __float22bfloat162_rn(make_float2(v.x, v.y));
        __nv_bfloat162 hi = __float22bfloat162_rn(make_float2(v.z, v.w));
        uint2 u; u.x = *(uint32_t*)&lo; u.y = *(uint32_t*)&hi;
        *(uint2*)(Bs + kr * 264 + q * 4) = u;
    }
    b2s[tid] = b2[tid];
    w3s[tid] = W3[tid];
    __syncthreads();

    uint32_t abase = smem_u32(As);
    uint32_t bbase = smem_u32(Bs);
    uint32_t a_addr0 = abase + (uint32_t)(wrow + (lane & 15)) * 144u + (uint32_t)(lane >> 4) * 16u;
    uint32_t b_addr0 = bbase + (uint32_t)((lane & 7) + ((lane >> 3) & 1) * 8) * 528u
                             + (uint32_t)(lane >> 4) * 16u;

    float rs0 = 0.f, rs1 = 0.f;

#pragma unroll
    for (int cg = 0; cg < 4; cg++) {
        float acc[8][4] = {};
#pragma unroll
        for (int ks = 0; ks < 4; ks++) {
            uint32_t a0, a1, a2, a3;
            LDSM_X4(a0, a1, a2, a3, a_addr0 + (uint32_t)ks * 32u);
            uint32_t b[8][2];
#pragma unroll
            for (int g = 0; g < 4; g++) {
                LDSM_X4T(b[2 * g][0], b[2 * g][1], b[2 * g + 1][0], b[2 * g + 1][1],
                         b_addr0 + (uint32_t)ks * 16u * 528u + (uint32_t)cg * 128u + (uint32_t)g * 32u);
            }
#pragma unroll
            for (int j = 0; j < 8; j++) MMA_BF16(acc[j], a0, a1, a2, a3, b[j][0], b[j][1]);
        }
#pragma unroll
        for (int j = 0; j < 8; j++) {
            int col = cg * 64 + j * 8 + (lane & 3) * 2;
            float v;
            v = fmaxf(acc[j][0] + b2s[col],     0.f); rs0 += v * w3s[col];
            v = fmaxf(acc[j][1] + b2s[col + 1], 0.f); rs0 += v * w3s[col + 1];
            v = fmaxf(acc[j][2] + b2s[col],     0.f); rs1 += v * w3s[col];
            v = fmaxf(acc[j][3] + b2s[col + 1], 0.f); rs1 += v * w3s[col + 1];
        }
    }
    rs0 += __shfl_xor_sync(0xffffffffu, rs0, 1);
    rs0 += __shfl_xor_sync(0xffffffffu, rs0, 2);
    rs1 += __shfl_xor_sync(0xffffffffu, rs1, 1);
    rs1 += __shfl_xor_sync(0xffffffffu, rs1, 2);
    if ((lane & 3) == 0) {
        int r = row0 + wrow + (lane >> 2);
        if (r < n)     g_zw[r]     = rs0;
        if (r + 8 < n) g_zw[r + 8] = rs1;
    }
}

// ---------------- layer-3 gather + BCE + block partials ----------------
__global__ void loss_k(const float* __restrict__ y, const float* __restrict__ b3, int n) {
    int i = blockIdx.x * 256 + threadIdx.x;
    float l = 0.f;
    if (i < n) {
        float di = g_deg[i];
        float acc = g_zw[i] * di * di;
        int p1 = g_offs[i + 1];
        for (int p = g_offs[i]; p < p1; p++) {
            int s = g_esrc[p];
            acc += g_zw[s] * g_deg[s] * di;
        }
        float zi = acc + b3[0];
        float yi = y[i];
        float l1p = log1pf(expf(-fabsf(zi)));
        float sp_pos = fmaxf(zi,  0.f) + l1p;
        float sp_neg = fmaxf(-zi, 0.f) + l1p;
        l = yi * sp_neg + (1.f - yi) * sp_pos;
    }
    __shared__ float sh[256];
    sh[threadIdx.x] = l;
    __syncthreads();
    for (int s = 128; s; s >>= 1) {
        if (threadIdx.x < s) sh[threadIdx.x] += sh[threadIdx.x + s];
        __syncthreads();
    }
    if (threadIdx.x == 0) g_lpart[blockIdx.x] = sh[0];
}

__global__ void finalize_k(float* out, int n, int nblk) {
    __shared__ float sh[512];
    int t = threadIdx.x;
    float s = 0.f;
    for (int i = t; i < nblk; i += 512) s += g_lpart[i];
    sh[t] = s;
    __syncthreads();
    for (int k = 256; k; k >>= 1) {
        if (t < k) sh[t] += sh[t + k];
        __syncthreads();
    }
    if (t == 0) out[0] = sh[0] * (1.0f / (float)n);
}

// ---------------- launch ----------------
extern "C" void kernel_launch(void* const* d_in, const int* in_sizes, int n_in,
                              void* d_out, int out_size) {
    const float* x  = (const float*)d_in[0];
    const int*   ei = (const int*)  d_in[1];
    const float* y  = (const float*)d_in[2];
    const float* W1 = (const float*)d_in[3];
    const float* b1 = (const float*)d_in[4];
    const float* W2 = (const float*)d_in[5];
    const float* b2 = (const float*)d_in[6];
    const float* W3 = (const float*)d_in[7];
    const float* b3 = (const float*)d_in[8];
    float* out = (float*)d_out;

    int n = in_sizes[0] / 512;
    int e = in_sizes[1] / 2;
    const int* src = ei;
    const int* dst = ei + e;

    int nb   = (n + 511) / 512;   // scan blocks (196)
    int nbl  = (n + 255) / 256;   // loss blocks (391)

    cudaFuncSetAttribute(gemm1_mma, cudaFuncAttributeMaxDynamicSharedMemorySize, G1_SMEM);
    cudaFuncSetAttribute(gemm2_mma, cudaFuncAttributeMaxDynamicSharedMemorySize, G2_SMEM);

    // ---- fork: GEMM1 on side stream, CSR preprocessing on main stream ----
    cudaEventRecord(g_ss.e0, 0);
    cudaStreamWaitEvent(g_ss.s1, g_ss.e0, 0);
    gemm1_mma<<<(n + 127) / 128, 256, G1_SMEM, g_ss.s1>>>(x, W1, n);

    init_k <<<(n + 255) / 256, 256>>>(n);
    count_k<<<(e + 255) / 256, 256>>>(dst, e);
    scanA_k<<<nb, 512>>>(n);
    scanC_k<<<nb, 512>>>(n, e);
    fill_k <<<(e + 255) / 256, 256>>>(src, dst, e);

    // ---- join ----
    cudaEventRecord(g_ss.e1, g_ss.s1);
    cudaStreamWaitEvent(0, g_ss.e1, 0);

    gather_h1 <<<(n + 7) / 8, 256>>>(b1, n);    // h1b = bf16(relu(A xw1 + b1))
    gather_agg<<<(n + 7) / 8, 256>>>(n);        // aggb = bf16(A h1)
    gemm2_mma<<<(n + 127) / 128, 256, G2_SMEM>>>(W2, b2, W3, n);
    loss_k<<<nbl, 256>>>(y, b3, n);
    finalize_k<<<1, 512>>>(out, n, nbl);
}

// round 8
// speedup vs baseline: 2.2942x; 1.0601x over previous
#include <cuda_runtime.h>
#include <cuda_bf16.h>
#include <cstdint>
#include <math.h>

#define N_MAX 100000
#define E_MAX 1600000

// ---------------- device scratch (static, no allocations) ----------------
__device__ __align__(256) __nv_bfloat16 g_xw1b[N_MAX * 64]; // x @ W1 (bf16)
__device__ __align__(256) __nv_bfloat16 g_h1b [N_MAX * 64]; // relu(agg(xw1)+b1) (bf16)
__device__ __align__(256) __nv_bfloat16 g_aggb[N_MAX * 64]; // agg(h1) (bf16)
__device__ __align__(256) float g_zw [N_MAX];               // fused gemm2+W3 output
__device__ __align__(256) float g_deg[N_MAX];               // dinv = rsqrt(deg)
__device__ int   g_cnt [N_MAX];
__device__ int   g_offs[N_MAX + 1];
__device__ int   g_pos [N_MAX];
__device__ int   g_esrc[E_MAX];
__device__ int   g_partial[1024];
__device__ float g_lpart[512];

// ---------------- static streams/events (created at load, before baseline) ----------------
struct SideStream {
    cudaStream_t s1;
    cudaEvent_t  e0, e1;
    SideStream() {
        cudaStreamCreateWithFlags(&s1, cudaStreamNonBlocking);
        cudaEventCreateWithFlags(&e0, cudaEventDisableTiming);
        cudaEventCreateWithFlags(&e1, cudaEventDisableTiming);
    }
};
static SideStream g_ss;

// ---------------- helpers ----------------
__device__ __forceinline__ uint32_t smem_u32(const void* p) {
    uint32_t a;
    asm("{ .reg .u64 t; cvta.to.shared.u64 t, %1; cvt.u32.u64 %0, t; }" : "=r"(a) : "l"(p));
    return a;
}

#define LDSM_X4(R0,R1,R2,R3,ADDR) \
    asm volatile("ldmatrix.sync.aligned.m8n8.x4.shared.b16 {%0,%1,%2,%3}, [%4];" \
        : "=r"(R0),"=r"(R1),"=r"(R2),"=r"(R3) : "r"(ADDR))

#define LDSM_X4T(R0,R1,R2,R3,ADDR) \
    asm volatile("ldmatrix.sync.aligned.m8n8.x4.trans.shared.b16 {%0,%1,%2,%3}, [%4];" \
        : "=r"(R0),"=r"(R1),"=r"(R2),"=r"(R3) : "r"(ADDR))

#define MMA_BF16(D,A0,A1,A2,A3,B0,B1) \
    asm volatile("mma.sync.aligned.m16n8k16.row.col.f32.bf16.bf16.f32 " \
        "{%0,%1,%2,%3}, {%4,%5,%6,%7}, {%8,%9}, {%0,%1,%2,%3};" \
        : "+f"((D)[0]),"+f"((D)[1]),"+f"((D)[2]),"+f"((D)[3]) \
        : "r"(A0),"r"(A1),"r"(A2),"r"(A3),"r"(B0),"r"(B1))

// ---------------- preprocessing ----------------
__global__ void init_k(int n) {
    int i = blockIdx.x * blockDim.x + threadIdx.x;
    if (i < n) g_cnt[i] = 0;
}

__global__ void count_k(const int* __restrict__ dst, int e) {
    int i = blockIdx.x * blockDim.x + threadIdx.x;
    if (i < e) atomicAdd(&g_cnt[dst[i]], 1);
}

__global__ void scanA_k(int n) {
    __shared__ int sh[512];
    int i = blockIdx.x * 512 + threadIdx.x;
    sh[threadIdx.x] = (i < n) ? g_cnt[i] : 0;
    __syncthreads();
    for (int s = 256; s; s >>= 1) {
        if (threadIdx.x < s) sh[threadIdx.x] += sh[threadIdx.x + s];
        __syncthreads();
    }
    if (threadIdx.x == 0) g_partial[blockIdx.x] = sh[0];
}

// scanC: per-block prefix over partials + intra-block scan
__global__ void scanC_k(int n, int e) {
    __shared__ int pre[512];
    __shared__ int sh[512];
    int t = threadIdx.x;
    pre[t] = (t < (int)blockIdx.x) ? g_partial[t] : 0;
    __syncthreads();
    for (int s = 256; s; s >>= 1) {
        if (t < s) pre[t] += pre[t + s];
        __syncthreads();
    }
    int blockOff = pre[0];

    int i = blockIdx.x * 512 + t;
    int orig = (i < n) ? g_cnt[i] : 0;
    sh[t] = orig;
    __syncthreads();
    for (int off = 1; off < 512; off <<= 1) {
        int v = (t >= off) ? sh[t - off] : 0;
        __syncthreads();
        sh[t] += v;
        __syncthreads();
    }
    if (i < n) {
        int excl = sh[t] - orig + blockOff;
        g_offs[i] = excl;
        g_pos[i]  = excl;
        g_deg[i]  = rsqrtf((float)orig + 1.0f);
    }
    if (i == 0) g_offs[n] = e;
}

__global__ void fill_k(const int* __restrict__ src, const int* __restrict__ dst, int e) {
    int i = blockIdx.x * blockDim.x + threadIdx.x;
    if (i < e) {
        int d = dst[i];
        int idx = atomicAdd(&g_pos[d], 1);
        g_esrc[idx] = src[i];
    }
}

// ---------------- GEMM1 (HMMA, double-buffered): xw1b = bf16(X @ W1) ----------------
#define G1_SMEM 55296

__global__ void __launch_bounds__(256) gemm1_mma(const float* __restrict__ X,
                                                 const float* __restrict__ W1, int n) {
    extern __shared__ char smem[];
    __nv_bfloat16* Abuf[2] = {(__nv_bfloat16*)(smem),         (__nv_bfloat16*)(smem + 18432)};
    __nv_bfloat16* Bbuf[2] = {(__nv_bfloat16*)(smem + 36864), (__nv_bfloat16*)(smem + 46080)};

    int tid  = threadIdx.x;
    int wid  = tid >> 5, lane = tid & 31;
    int row0 = blockIdx.x * 128;
    int wrow = wid * 16;

    uint32_t a_base[2], b_base[2];
#pragma unroll
    for (int b = 0; b < 2; b++) {
        a_base[b] = smem_u32(Abuf[b]) + (uint32_t)(wrow + (lane & 15)) * 144u + (uint32_t)(lane >> 4) * 16u;
        b_base[b] = smem_u32(Bbuf[b]) + (uint32_t)((lane & 7) + ((lane >> 3) & 1) * 8) * 144u
                                      + (uint32_t)(lane >> 4) * 16u;
    }

    int ar[8], aq[8];
    const float* aptr[8];
#pragma unroll
    for (int it = 0; it < 8; it++) {
        int f = tid + it * 256;
        ar[it] = f >> 4; aq[it] = f & 15;
        int gr = row0 + ar[it]; if (gr >= n) gr = n - 1;
        aptr[it] = X + (size_t)gr * 512 + aq[it] * 4;
    }
    int bkr[4], bq[4];
#pragma unroll
    for (int it = 0; it < 4; it++) {
        int f = tid + it * 256;
        bkr[it] = f >> 4; bq[it] = f & 15;
    }

    float4 pa[8], pb[4];
#pragma unroll
    for (int it = 0; it < 8; it++) pa[it] = *(const float4*)(aptr[it]);
#pragma unroll
    for (int it = 0; it < 4; it++) pb[it] = *(const float4*)(W1 + (size_t)bkr[it] * 64 + bq[it] * 4);

    float acc[8][4] = {};

    for (int c = 0; c < 8; c++) {
        int buf = c & 1;
        __nv_bfloat16* As = Abuf[buf];
        __nv_bfloat16* Bs = Bbuf[buf];
#pragma unroll
        for (int it = 0; it < 8; it++) {
            __nv_bfloat162 lo = __float22bfloat162_rn(make_float2(pa[it].x, pa[it].y));
            __nv_bfloat162 hi = __float22bfloat162_rn(make_float2(pa[it].z, pa[it].w));
            uint2 u; u.x = *(uint32_t*)&lo; u.y = *(uint32_t*)&hi;
            *(uint2*)(As + ar[it] * 72 + aq[it] * 4) = u;
        }
#pragma unroll
        for (int it = 0; it < 4; it++) {
            __nv_bfloat162 lo = __float22bfloat162_rn(make_float2(pb[it].x, pb[it].y));
            __nv_bfloat162 hi = __float22bfloat162_rn(make_float2(pb[it].z, pb[it].w));
            uint2 u; u.x = *(uint32_t*)&lo; u.y = *(uint32_t*)&hi;
            *(uint2*)(Bs + bkr[it] * 72 + bq[it] * 4) = u;
        }
        __syncthreads();
        if (c < 7) {
            int k0 = (c + 1) * 64;
#pragma unroll
            for (int it = 0; it < 8; it++) pa[it] = *(const float4*)(aptr[it] + k0);
#pragma unroll
            for (int it = 0; it < 4; it++)
                pb[it] = *(const float4*)(W1 + (size_t)(k0 + bkr[it]) * 64 + bq[it] * 4);
        }
#pragma unroll
        for (int ks = 0; ks < 4; ks++) {
            uint32_t a0, a1, a2, a3;
            LDSM_X4(a0, a1, a2, a3, a_base[buf] + (uint32_t)ks * 32u);
            uint32_t b[8][2];
#pragma unroll
            for (int g = 0; g < 4; g++) {
                LDSM_X4T(b[2 * g][0], b[2 * g][1], b[2 * g + 1][0], b[2 * g + 1][1],
                         b_base[buf] + (uint32_t)ks * 16u * 144u + (uint32_t)g * 32u);
            }
#pragma unroll
            for (int j = 0; j < 8; j++) MMA_BF16(acc[j], a0, a1, a2, a3, b[j][0], b[j][1]);
        }
        __syncthreads();
    }
    int rbase = row0 + wrow + (lane >> 2);
    int cbase = (lane & 3) * 2;
#pragma unroll
    for (int j = 0; j < 8; j++) {
        int col = j * 8 + cbase;
        if (rbase < n) {
            __nv_bfloat162 v = __float22bfloat162_rn(make_float2(acc[j][0], acc[j][1]));
            *(uint32_t*)(g_xw1b + (size_t)rbase * 64 + col) = *(uint32_t*)&v;
        }
        if (rbase + 8 < n) {
            __nv_bfloat162 v = __float22bfloat162_rn(make_float2(acc[j][2], acc[j][3]));
            *(uint32_t*)(g_xw1b + (size_t)(rbase + 8) * 64 + col) = *(uint32_t*)&v;
        }
    }
}

// ---------------- MLP-4 gathers: warp per node, 4 edges in flight ----------------
// lane group g = lane>>3 handles edge p+g; slice sl = lane&7 covers 8 bf16 (16B).
__device__ __forceinline__ void acc_row8(float2 (&acc)[4], uint4 u, float wgt) {
    float2 v;
    v = __bfloat1622float2(*(__nv_bfloat162*)&u.x); acc[0].x += v.x * wgt; acc[0].y += v.y * wgt;
    v = __bfloat1622float2(*(((__nv_bfloat162*)&u.x) + 1)); acc[1].x += v.x * wgt; acc[1].y += v.y * wgt;
    v = __bfloat1622float2(*(__nv_bfloat162*)&u.z); acc[2].x += v.x * wgt; acc[2].y += v.y * wgt;
    v = __bfloat1622float2(*(((__nv_bfloat162*)&u.z) + 1)); acc[3].x += v.x * wgt; acc[3].y += v.y * wgt;
}

template<int EPI>  // EPI=1: relu(+bias), EPI=0: plain
__device__ __forceinline__ void gather64(const __nv_bfloat16* __restrict__ in,
                                         __nv_bfloat16* __restrict__ out,
                                         const float* __restrict__ bias, int n) {
    int w    = (blockIdx.x * blockDim.x + threadIdx.x) >> 5;
    int lane = threadIdx.x & 31;
    if (w >= n) return;
    int g  = lane >> 3;
    int sl = lane & 7;
    float di = g_deg[w];

    float2 acc[4] = {};
    // self loop (group 0 only carries the weight; others add 0)
    {
        uint4 u = ((const uint4*)(in + (size_t)w * 64))[sl];
        float ws = (g == 0) ? di * di : 0.f;
        acc_row8(acc, u, ws);
    }
    int p0 = g_offs[w];
    int p1 = g_offs[w + 1];
    for (int p = p0; p < p1; p += 4) {
        int  pe = p + g;
        bool ok = pe < p1;
        int  s  = ok ? g_esrc[pe] : w;
        float wgt = ok ? g_deg[s] * di : 0.f;
        uint4 u = ((const uint4*)(in + (size_t)s * 64))[sl];
        acc_row8(acc, u, wgt);
    }
    // combine the 4 groups
#pragma unroll
    for (int i = 0; i < 4; i++) {
        acc[i].x += __shfl_xor_sync(0xffffffffu, acc[i].x, 8);
        acc[i].y += __shfl_xor_sync(0xffffffffu, acc[i].y, 8);
        acc[i].x += __shfl_xor_sync(0xffffffffu, acc[i].x, 16);
        acc[i].y += __shfl_xor_sync(0xffffffffu, acc[i].y, 16);
    }
    if (lane < 8) {
        uint4 o;
        uint32_t* op = (uint32_t*)&o;
#pragma unroll
        for (int i = 0; i < 4; i++) {
            float2 v = acc[i];
            if (EPI) {
                int c = sl * 8 + i * 2;
                v.x = fmaxf(v.x + bias[c],     0.f);
                v.y = fmaxf(v.y + bias[c + 1], 0.f);
            }
            __nv_bfloat162 b = __float22bfloat162_rn(v);
            op[i] = *(uint32_t*)&b;
        }
        ((uint4*)(out + (size_t)w * 64))[sl] = o;
    }
}

__global__ void gather_h1(const float* __restrict__ bias, int n) {
    gather64<1>(g_xw1b, g_h1b, bias, n);
}
__global__ void gather_agg(int n) {
    gather64<0>(g_h1b, g_aggb, (const float*)nullptr, n);
}

// ---------------- GEMM2 (HMMA) fused: zw[row] = relu(aggb@W2 + b2) . W3 ----------------
#define G2_SMEM 54272

__global__ void __launch_bounds__(256) gemm2_mma(const float* __restrict__ W2,
                                                 const float* __restrict__ b2,
                                                 const float* __restrict__ W3, int n) {
    extern __shared__ char smem[];
    __nv_bfloat16* As  = (__nv_bfloat16*)(smem);
    __nv_bfloat16* Bs  = (__nv_bfloat16*)(smem + 18432);
    float*         b2s = (float*)(smem + 52224);
    float*         w3s = (float*)(smem + 53248);

    int tid  = threadIdx.x;
    int wid  = tid >> 5, lane = tid & 31;
    int row0 = blockIdx.x * 128;
    int wrow = wid * 16;

#pragma unroll
    for (int it = 0; it < 8; it++) {
        int f = tid + it * 256;
        int r = f >> 4, q = f & 15;
        int gr = row0 + r; if (gr >= n) gr = n - 1;
        uint2 u = ((const uint2*)(g_aggb + (size_t)gr * 64))[q];
        *(uint2*)(As + r * 72 + q * 4) = u;
    }
#pragma unroll
    for (int it = 0; it < 16; it++) {
        int f = tid + it * 256;
        int kr = f >> 6, q = f & 63;
        float4 v = *(const float4*)(W2 + (size_t)kr * 256 + q * 4);
        __nv_bfloat162 lo = __float22bfloat162_rn(make_float2(v.x, v.y));
        __nv_bfloat162 hi = __float22bfloat162_rn(make_float2(v.z, v.w));
        uint2 u; u.x = *(uint32_t*)&lo; u.y = *(uint32_t*)&hi;
        *(uint2*)(Bs + kr * 264 + q * 4) = u;
    }
    b2s[tid] = b2[tid];
    w3s[tid] = W3[tid];
    __syncthreads();

    uint32_t abase = smem_u32(As);
    uint32_t bbase = smem_u32(Bs);
    uint32_t a_addr0 = abase + (uint32_t)(wrow + (lane & 15)) * 144u + (uint32_t)(lane >> 4) * 16u;
    uint32_t b_addr0 = bbase + (uint32_t)((lane & 7) + ((lane >> 3) & 1) * 8) * 528u
                             + (uint32_t)(lane >> 4) * 16u;

    float rs0 = 0.f, rs1 = 0.f;

#pragma unroll
    for (int cg = 0; cg < 4; cg++) {
        float acc[8][4] = {};
#pragma unroll
        for (int ks = 0; ks < 4; ks++) {
            uint32_t a0, a1, a2, a3;
            LDSM_X4(a0, a1, a2, a3, a_addr0 + (uint32_t)ks * 32u);
            uint32_t b[8][2];
#pragma unroll
            for (int g = 0; g < 4; g++) {
                LDSM_X4T(b[2 * g][0], b[2 * g][1], b[2 * g + 1][0], b[2 * g + 1][1],
                         b_addr0 + (uint32_t)ks * 16u * 528u + (uint32_t)cg * 128u + (uint32_t)g * 32u);
            }
#pragma unroll
            for (int j = 0; j < 8; j++) MMA_BF16(acc[j], a0, a1, a2, a3, b[j][0], b[j][1]);
        }
#pragma unroll
        for (int j = 0; j < 8; j++) {
            int col = cg * 64 + j * 8 + (lane & 3) * 2;
            float v;
            v = fmaxf(acc[j][0] + b2s[col],     0.f); rs0 += v * w3s[col];
            v = fmaxf(acc[j][1] + b2s[col + 1], 0.f); rs0 += v * w3s[col + 1];
            v = fmaxf(acc[j][2] + b2s[col],     0.f); rs1 += v * w3s[col];
            v = fmaxf(acc[j][3] + b2s[col + 1], 0.f); rs1 += v * w3s[col + 1];
        }
    }
    rs0 += __shfl_xor_sync(0xffffffffu, rs0, 1);
    rs0 += __shfl_xor_sync(0xffffffffu, rs0, 2);
    rs1 += __shfl_xor_sync(0xffffffffu, rs1, 1);
    rs1 += __shfl_xor_sync(0xffffffffu, rs1, 2);
    if ((lane & 3) == 0) {
        int r = row0 + wrow + (lane >> 2);
        if (r < n)     g_zw[r]     = rs0;
        if (r + 8 < n) g_zw[r + 8] = rs1;
    }
}

// ---------------- layer-3 gather + BCE + block partials ----------------
__global__ void loss_k(const float* __restrict__ y, const float* __restrict__ b3, int n) {
    int i = blockIdx.x * 256 + threadIdx.x;
    float l = 0.f;
    if (i < n) {
        float di = g_deg[i];
        float acc = g_zw[i] * di * di;
        int p  = g_offs[i];
        int p1 = g_offs[i + 1];
#pragma unroll 4
        for (; p < p1; p++) {
            int s = g_esrc[p];
            acc += g_zw[s] * g_deg[s] * di;
        }
        float zi = acc + b3[0];
        float yi = y[i];
        float l1p = log1pf(expf(-fabsf(zi)));
        float sp_pos = fmaxf(zi,  0.f) + l1p;
        float sp_neg = fmaxf(-zi, 0.f) + l1p;
        l = yi * sp_neg + (1.f - yi) * sp_pos;
    }
    __shared__ float sh[256];
    sh[threadIdx.x] = l;
    __syncthreads();
    for (int s = 128; s; s >>= 1) {
        if (threadIdx.x < s) sh[threadIdx.x] += sh[threadIdx.x + s];
        __syncthreads();
    }
    if (threadIdx.x == 0) g_lpart[blockIdx.x] = sh[0];
}

__global__ void finalize_k(float* out, int n, int nblk) {
    __shared__ float sh[512];
    int t = threadIdx.x;
    float s = 0.f;
    for (int i = t; i < nblk; i += 512) s += g_lpart[i];
    sh[t] = s;
    __syncthreads();
    for (int k = 256; k; k >>= 1) {
        if (t < k) sh[t] += sh[t + k];
        __syncthreads();
    }
    if (t == 0) out[0] = sh[0] * (1.0f / (float)n);
}

// ---------------- launch ----------------
extern "C" void kernel_launch(void* const* d_in, const int* in_sizes, int n_in,
                              void* d_out, int out_size) {
    const float* x  = (const float*)d_in[0];
    const int*   ei = (const int*)  d_in[1];
    const float* y  = (const float*)d_in[2];
    const float* W1 = (const float*)d_in[3];
    const float* b1 = (const float*)d_in[4];
    const float* W2 = (const float*)d_in[5];
    const float* b2 = (const float*)d_in[6];
    const float* W3 = (const float*)d_in[7];
    const float* b3 = (const float*)d_in[8];
    float* out = (float*)d_out;

    int n = in_sizes[0] / 512;
    int e = in_sizes[1] / 2;
    const int* src = ei;
    const int* dst = ei + e;

    int nb   = (n + 511) / 512;   // scan blocks
    int nbl  = (n + 255) / 256;   // loss blocks

    cudaFuncSetAttribute(gemm1_mma, cudaFuncAttributeMaxDynamicSharedMemorySize, G1_SMEM);
    cudaFuncSetAttribute(gemm2_mma, cudaFuncAttributeMaxDynamicSharedMemorySize, G2_SMEM);

    // ---- fork: GEMM1 on side stream, CSR preprocessing on main stream ----
    cudaEventRecord(g_ss.e0, 0);
    cudaStreamWaitEvent(g_ss.s1, g_ss.e0, 0);
    gemm1_mma<<<(n + 127) / 128, 256, G1_SMEM, g_ss.s1>>>(x, W1, n);

    init_k <<<(n + 255) / 256, 256>>>(n);
    count_k<<<(e + 255) / 256, 256>>>(dst, e);
    scanA_k<<<nb, 512>>>(n);
    scanC_k<<<nb, 512>>>(n, e);
    fill_k <<<(e + 255) / 256, 256>>>(src, dst, e);

    // ---- join ----
    cudaEventRecord(g_ss.e1, g_ss.s1);
    cudaStreamWaitEvent(0, g_ss.e1, 0);

    gather_h1 <<<(n + 7) / 8, 256>>>(b1, n);    // h1b = bf16(relu(A xw1 + b1))
    gather_agg<<<(n + 7) / 8, 256>>>(n);        // aggb = bf16(A h1)
    gemm2_mma<<<(n + 127) / 128, 256, G2_SMEM>>>(W2, b2, W3, n);
    loss_k<<<nbl, 256>>>(y, b3, n);
    finalize_k<<<1, 512>>>(out, n, nbl);
}